// round 16
// baseline (speedup 1.0000x reference)
#include <cuda_runtime.h>
#include <cuda_fp16.h>

#define NN 100000
#define NE 3200000
#define DF 512
#define NH 16
#define NC 40
#define NSCAN ((NN + 1023) / 1024)   // 98

// ---------------- device scratch (no allocs allowed) ----------------
// g_deg/g_cnt zeroed by k_gather1 each run; g_sflag zeroed by k_fill.
__device__ float   g_deg [NN];      // Σ incoming w (self-loop +1 folded into dinv)
__device__ float   g_dinv[NN];
__device__ int     g_cnt [NN];      // per-node in-degree count
__device__ int     g_off [NN + 1];  // CSR exclusive offsets
__device__ int     g_cur [NN];      // fill cursors (re-init by k_scan each run)
__device__ int     g_sval[128];     // scan block totals
__device__ int     g_sflag[128];    // scan publish flags
__device__ int2    g_edge[NE];      // CSR: (src, dinv[src]*w as int) per slot
__device__ __half2 g_h  [NN * 8];   // x @ W1                (fp16, 8 half2/row)
__device__ __half2 g_h1 [NN * 8];   // relu(propagate(h)+b1) (fp16)

// ------------- count + weighted degree (4 edges/thread) -------------------
__global__ void k_count(const int* __restrict__ col,
                        const float* __restrict__ w) {
    int t = blockIdx.x * blockDim.x + threadIdx.x;   // over NE/4
    if (t >= NE / 4) return;
    int4   c4 = reinterpret_cast<const int4*>(col)[t];
    float4 w4 = reinterpret_cast<const float4*>(w)[t];
    atomicAdd(&g_cnt[c4.x], 1);  atomicAdd(&g_deg[c4.x], w4.x);
    atomicAdd(&g_cnt[c4.y], 1);  atomicAdd(&g_deg[c4.y], w4.y);
    atomicAdd(&g_cnt[c4.z], 1);  atomicAdd(&g_deg[c4.z], w4.z);
    atomicAdd(&g_cnt[c4.w], 1);  atomicAdd(&g_deg[c4.w], w4.w);
}

// ------- single-pass scan: exclusive offsets + cursors + dinv -------------
__global__ void __launch_bounds__(1024) k_scan() {
    __shared__ int s[1024];
    __shared__ int sb[128];
    const int t = threadIdx.x;
    const int b = blockIdx.x;
    const int i = b * 1024 + t;

    int v = (i < NN) ? g_cnt[i] : 0;
    s[t] = v;
    __syncthreads();
#pragma unroll
    for (int off = 1; off < 1024; off <<= 1) {
        int u = (t >= off) ? s[t - off] : 0;
        __syncthreads();
        s[t] += u;
        __syncthreads();
    }
    if (t == 0) {
        g_sval[b] = s[1023];
        __threadfence();
        *((volatile int*)&g_sflag[b]) = 1;
    }
    int pv = 0;
    if (t < 128) {
        if (t < b) {
            while (*((volatile int*)&g_sflag[t]) == 0) { }
            __threadfence();
            pv = g_sval[t];
        }
        sb[t] = pv;
    }
    __syncthreads();
#pragma unroll
    for (int off = 64; off > 0; off >>= 1) {
        if (t < off) sb[t] += sb[t + off];
        __syncthreads();
    }
    int pref = sb[0];

    if (i < NN) {
        int excl = pref + s[t] - v;             // exclusive global offset
        g_off[i]  = excl;
        g_cur[i]  = excl;                       // fill cursor
        g_dinv[i] = rsqrtf(1.0f + g_deg[i]);    // +1 = self-loop weight
    }
    if (i == 0) g_off[NN] = NE;
}

// ---------------- fill CSR (4 edges/thread), cursor atomics ---------------
// meta = (src, dinv[src]*w): dinv[dst] is applied inside the gathers, so
// fill does only ONE random load (dinv[r]) + one cursor atomic per edge.
__global__ void k_fill(const int* __restrict__ row,
                       const int* __restrict__ col,
                       const float* __restrict__ w) {
    int t = blockIdx.x * blockDim.x + threadIdx.x;   // over NE/4
    if (t < 128) g_sflag[t] = 0;                     // reset for next replay
    if (t >= NE / 4) return;
    int4   r4 = reinterpret_cast<const int4*>(row)[t];
    int4   c4 = reinterpret_cast<const int4*>(col)[t];
    float4 w4 = reinterpret_cast<const float4*>(w)[t];

    int p;
    p = atomicAdd(&g_cur[c4.x], 1);
    g_edge[p] = make_int2(r4.x, __float_as_int(g_dinv[r4.x] * w4.x));
    p = atomicAdd(&g_cur[c4.y], 1);
    g_edge[p] = make_int2(r4.y, __float_as_int(g_dinv[r4.y] * w4.y));
    p = atomicAdd(&g_cur[c4.z], 1);
    g_edge[p] = make_int2(r4.z, __float_as_int(g_dinv[r4.z] * w4.z));
    p = atomicAdd(&g_cur[c4.w], 1);
    g_edge[p] = make_int2(r4.w, __float_as_int(g_dinv[r4.w] * w4.w));
}

// ---------------- GEMM1: h = x @ W1   (100000x512 @ 512x16) ----------------
// R12 version (best measured: 86.9us). 128 rows/block, 2 threads/row x 8 cols,
// register double-buffered LDG pipeline, transposed smem stride 129, fp16 out.
__global__ void __launch_bounds__(256) k_gemm1(const float* __restrict__ x,
                                               const float* __restrict__ W1) {
    __shared__ float  Xs[32 * 129];   // [kk][r], stride 129: conflict-free
    __shared__ float4 Ws4[128];       // 32 x 16 W chunk as float4

    const int tid  = threadIdx.x;
    const int rloc = tid & 127;
    const int half = tid >> 7;                 // 0: j 0..7, 1: j 8..15
    const int row0 = blockIdx.x * 128;
    const int row  = row0 + rloc;

    float acc[8];
#pragma unroll
    for (int j = 0; j < 8; j++) acc[j] = 0.0f;

    float4 buf[4];
#pragma unroll
    for (int i = 0; i < 4; i++) {
        int idx = i * 256 + tid;
        int r   = idx >> 3;
        int q   = idx & 7;
        int gr  = row0 + r;
        buf[i] = (gr < NN)
            ? *reinterpret_cast<const float4*>(x + (size_t)gr * DF + q * 4)
            : make_float4(0.f, 0.f, 0.f, 0.f);
    }

    for (int c = 0; c < DF / 32; c++) {
        __syncthreads();
#pragma unroll
        for (int i = 0; i < 4; i++) {
            int idx = i * 256 + tid;
            int r   = idx >> 3;
            int kk  = (idx & 7) * 4;
            Xs[(kk + 0) * 129 + r] = buf[i].x;
            Xs[(kk + 1) * 129 + r] = buf[i].y;
            Xs[(kk + 2) * 129 + r] = buf[i].z;
            Xs[(kk + 3) * 129 + r] = buf[i].w;
        }
        if (tid < 128)
            Ws4[tid] = reinterpret_cast<const float4*>(W1)[c * 128 + tid];
        __syncthreads();

        if (c < DF / 32 - 1) {
#pragma unroll
            for (int i = 0; i < 4; i++) {
                int idx = i * 256 + tid;
                int r   = idx >> 3;
                int q   = idx & 7;
                int gr  = row0 + r;
                buf[i] = (gr < NN)
                    ? *reinterpret_cast<const float4*>(
                          x + (size_t)gr * DF + (c + 1) * 32 + q * 4)
                    : make_float4(0.f, 0.f, 0.f, 0.f);
            }
        }

#pragma unroll
        for (int kk = 0; kk < 32; kk++) {
            float  xv = Xs[kk * 129 + rloc];
            float4 w0 = Ws4[kk * 4 + half * 2 + 0];
            float4 w1 = Ws4[kk * 4 + half * 2 + 1];
            acc[0] += xv * w0.x;  acc[1] += xv * w0.y;
            acc[2] += xv * w0.z;  acc[3] += xv * w0.w;
            acc[4] += xv * w1.x;  acc[5] += xv * w1.y;
            acc[6] += xv * w1.z;  acc[7] += xv * w1.w;
        }
    }

    if (row < NN) {
        __half2 p0 = __floats2half2_rn(acc[0], acc[1]);
        __half2 p1 = __floats2half2_rn(acc[2], acc[3]);
        __half2 p2 = __floats2half2_rn(acc[4], acc[5]);
        __half2 p3 = __floats2half2_rn(acc[6], acc[7]);
        __half2* hp = &g_h[row * 8 + half * 4];
        reinterpret_cast<uint4*>(hp)[0] =
            make_uint4(*reinterpret_cast<unsigned*>(&p0),
                       *reinterpret_cast<unsigned*>(&p1),
                       *reinterpret_cast<unsigned*>(&p2),
                       *reinterpret_cast<unsigned*>(&p3));
    }
}

// ---------------- cooperative gather (fp16 src): 4 lanes per node ---------
// meta.y = dinv[src]*w; dst-side dinv applied once to the edge sum:
// out = d * Σ nm·h[src]  +  d² · h[n]
__device__ __forceinline__ float4 gather_quarter_h2(const __half2* __restrict__ src,
                                                    int n, int q, unsigned gmask,
                                                    int base) {
    float d = g_dinv[n];
    uint2 raw = *reinterpret_cast<const uint2*>(&src[n * 8 + q * 2]);
    float2 lo = __half22float2(*reinterpret_cast<__half2*>(&raw.x));
    float2 hi = __half22float2(*reinterpret_cast<__half2*>(&raw.y));
    float4 accE = make_float4(0.f, 0.f, 0.f, 0.f);   // edge sum (un-scaled)

    int k0  = g_off[n];
    int end = g_off[n + 1];
    for (int k = k0; k < end; k += 4) {
        int kk = k + q;
        int2 e = (kk < end) ? g_edge[kk] : make_int2(0, 0);   // norm 0 -> no-op
#pragma unroll
        for (int j = 0; j < 4; j++) {
            int   rs = __shfl_sync(gmask, e.x, base + j);
            float nm = __shfl_sync(gmask, __int_as_float(e.y), base + j);
            uint2 v = *reinterpret_cast<const uint2*>(&src[rs * 8 + q * 2]);
            float2 vlo = __half22float2(*reinterpret_cast<__half2*>(&v.x));
            float2 vhi = __half22float2(*reinterpret_cast<__half2*>(&v.y));
            accE.x += nm * vlo.x;
            accE.y += nm * vlo.y;
            accE.z += nm * vhi.x;
            accE.w += nm * vhi.y;
        }
    }
    float s = d * d;
    return make_float4(d * accE.x + s * lo.x,
                       d * accE.y + s * lo.y,
                       d * accE.z + s * hi.x,
                       d * accE.w + s * hi.y);
}

// ---------------- layer-1 propagate (+bias+relu): g_h -> g_h1 -------------
// Also resets g_cnt / g_deg (consumed by k_scan) for the next graph replay.
__global__ void k_gather1(const float* __restrict__ b1) {
    int t = blockIdx.x * blockDim.x + threadIdx.x;   // over NN*4
    if (t >= NN * 4) return;
    int n = t >> 2;
    int q = t & 3;
    if (q == 0) { g_cnt[n] = 0; g_deg[n] = 0.0f; }   // state reset for next run
    int lane = threadIdx.x & 31;
    int base = lane & ~3;
    unsigned gmask = 0xFu << base;

    float4 acc = gather_quarter_h2(g_h, n, q, gmask, base);
    float4 bb = reinterpret_cast<const float4*>(b1)[q];
    float4 o;
    o.x = fmaxf(acc.x + bb.x, 0.0f);
    o.y = fmaxf(acc.y + bb.y, 0.0f);
    o.z = fmaxf(acc.z + bb.z, 0.0f);
    o.w = fmaxf(acc.w + bb.w, 0.0f);
    __half2 p0 = __floats2half2_rn(o.x, o.y);
    __half2 p1 = __floats2half2_rn(o.z, o.w);
    reinterpret_cast<uint2*>(&g_h1[n * 8 + q * 2])[0] =
        make_uint2(*reinterpret_cast<unsigned*>(&p0),
                   *reinterpret_cast<unsigned*>(&p1));
}

// ---------------- layer-2 propagate fused with GEMM2 ----------------------
__global__ void __launch_bounds__(256) k_gather2_gemm2(
        const float* __restrict__ W2,
        const float* __restrict__ b2,
        float* __restrict__ out) {
    __shared__ float W2s[NH * NC];   // 640 floats
    __shared__ float b2s[NC];

    int tid = threadIdx.x;
#pragma unroll
    for (int i = tid; i < NH * NC; i += 256) W2s[i] = W2[i];
    if (tid < NC) b2s[tid] = b2[tid];
    __syncthreads();

    int t  = blockIdx.x * blockDim.x + tid;          // over NN*4 (padded)
    int n  = t >> 2;
    int q  = t & 3;
    bool valid = (n < NN);
    int nc = valid ? n : (NN - 1);                   // clamp: keep lanes alive
    int lane = tid & 31;
    int base = lane & ~3;
    unsigned gmask = 0xFu << base;

    float4 acc = gather_quarter_h2(g_h1, nc, q, gmask, base);

    // exchange quarters among the 4 node-lanes
    float hv[NH];
#pragma unroll
    for (int j = 0; j < 4; j++) {
        hv[j * 4 + 0] = __shfl_sync(gmask, acc.x, base + j);
        hv[j * 4 + 1] = __shfl_sync(gmask, acc.y, base + j);
        hv[j * 4 + 2] = __shfl_sync(gmask, acc.z, base + j);
        hv[j * 4 + 3] = __shfl_sync(gmask, acc.w, base + j);
    }

    // each lane: 10 columns [q*10, q*10+10)
    float o[10];
#pragma unroll
    for (int j = 0; j < 10; j++) o[j] = b2s[q * 10 + j];
#pragma unroll
    for (int k = 0; k < NH; k++) {
        float hk = hv[k];
        const float* wr = &W2s[k * NC + q * 10];
#pragma unroll
        for (int j = 0; j < 10; j++) o[j] += hk * wr[j];
    }

    if (valid) {
        float* op = out + (size_t)n * NC + q * 10;   // 8B aligned
#pragma unroll
        for (int j = 0; j < 5; j++)
            reinterpret_cast<float2*>(op)[j] = make_float2(o[2*j], o[2*j+1]);
    }
}

// ---------------- launch ----------------
// Fork-join overlap, R11 submission order (gemm1 first on side stream).
// Profiler slot 4 = k_fill -> direct verification of the fill traffic cut.
extern "C" void kernel_launch(void* const* d_in, const int* in_sizes, int n_in,
                              void* d_out, int out_size) {
    const float* x  = (const float*)d_in[0];
    const int*   ei = (const int*)  d_in[1];   // [2, NE]
    const float* w  = (const float*)d_in[2];
    const float* W1 = (const float*)d_in[3];
    const float* b1 = (const float*)d_in[4];
    const float* W2 = (const float*)d_in[5];
    const float* b2 = (const float*)d_in[6];
    float* out = (float*)d_out;

    const int* row = ei;
    const int* col = ei + NE;

    const int TB = 256;
    const int gE4 = (NE / 4 + TB - 1) / TB;          // 3125
    const int gN4 = (NN * 4 + TB - 1) / TB;          // 1563
    const int gG1 = (NN + 127) / 128;                // 782

    cudaStream_t s1;
    cudaStreamCreateWithFlags(&s1, cudaStreamNonBlocking);
    cudaEvent_t eFork, eJoin;
    cudaEventCreateWithFlags(&eFork, cudaEventDisableTiming);
    cudaEventCreateWithFlags(&eJoin, cudaEventDisableTiming);

    // fork: gemm1 on side stream (submission 1), concurrent with build
    cudaEventRecord(eFork, 0);
    cudaStreamWaitEvent(s1, eFork, 0);
    k_gemm1<<<gG1, TB, 0, s1>>>(x, W1);
    cudaEventRecord(eJoin, s1);

    // CSR build on main stream (submissions 2-4; slot 4 = fill -> profiled)
    k_count<<<gE4, TB>>>(col, w);
    k_scan <<<NSCAN, 1024>>>();
    k_fill <<<gE4, TB>>>(row, col, w);

    // join: gathers need both g_h (gemm1) and CSR
    cudaStreamWaitEvent(0, eJoin, 0);
    k_gather1<<<gN4, TB>>>(b1);
    k_gather2_gemm2<<<gN4, TB>>>(W2, b2, out);
}

// round 17
// speedup vs baseline: 1.2261x; 1.2261x over previous
#include <cuda_runtime.h>
#include <cuda_fp16.h>

#define NN 100000
#define NE 3200000
#define DF 512
#define NH 16
#define NC 40
#define NSCAN ((NN + 1023) / 1024)   // 98

// ---------------- device scratch (no allocs allowed) ----------------
// g_deg/g_cnt zeroed by k_gather1 each run; g_sflag zeroed by k_fill.
__device__ float   g_deg [NN];      // Σ incoming w (self-loop +1 folded into dinv)
__device__ float   g_dinv[NN];
__device__ int     g_cnt [NN];      // per-node in-degree count
__device__ int     g_off [NN + 1];  // CSR exclusive offsets
__device__ int     g_cur [NN];      // fill cursors (re-init by k_scan each run)
__device__ int     g_sval[128];     // scan block totals
__device__ int     g_sflag[128];    // scan publish flags
__device__ int2    g_edge[NE];      // CSR: (src, dinv[src]*w as int) per slot
__device__ __half2 g_h  [NN * 8];   // x @ W1                (fp16, 8 half2/row)
__device__ __half2 g_h1 [NN * 8];   // relu(propagate(h)+b1) (fp16)

// ------------- count + weighted degree (4 edges/thread) -------------------
__global__ void k_count(const int* __restrict__ col,
                        const float* __restrict__ w) {
    int t = blockIdx.x * blockDim.x + threadIdx.x;   // over NE/4
    if (t >= NE / 4) return;
    int4   c4 = reinterpret_cast<const int4*>(col)[t];
    float4 w4 = reinterpret_cast<const float4*>(w)[t];
    atomicAdd(&g_cnt[c4.x], 1);  atomicAdd(&g_deg[c4.x], w4.x);
    atomicAdd(&g_cnt[c4.y], 1);  atomicAdd(&g_deg[c4.y], w4.y);
    atomicAdd(&g_cnt[c4.z], 1);  atomicAdd(&g_deg[c4.z], w4.z);
    atomicAdd(&g_cnt[c4.w], 1);  atomicAdd(&g_deg[c4.w], w4.w);
}

// ------- single-pass scan: exclusive offsets + cursors + dinv -------------
__global__ void __launch_bounds__(1024) k_scan() {
    __shared__ int s[1024];
    __shared__ int sb[128];
    const int t = threadIdx.x;
    const int b = blockIdx.x;
    const int i = b * 1024 + t;

    int v = (i < NN) ? g_cnt[i] : 0;
    s[t] = v;
    __syncthreads();
#pragma unroll
    for (int off = 1; off < 1024; off <<= 1) {
        int u = (t >= off) ? s[t - off] : 0;
        __syncthreads();
        s[t] += u;
        __syncthreads();
    }
    if (t == 0) {
        g_sval[b] = s[1023];
        __threadfence();
        *((volatile int*)&g_sflag[b]) = 1;
    }
    int pv = 0;
    if (t < 128) {
        if (t < b) {
            while (*((volatile int*)&g_sflag[t]) == 0) { }
            __threadfence();
            pv = g_sval[t];
        }
        sb[t] = pv;
    }
    __syncthreads();
#pragma unroll
    for (int off = 64; off > 0; off >>= 1) {
        if (t < off) sb[t] += sb[t + off];
        __syncthreads();
    }
    int pref = sb[0];

    if (i < NN) {
        int excl = pref + s[t] - v;             // exclusive global offset
        g_off[i]  = excl;
        g_cur[i]  = excl;                       // fill cursor
        g_dinv[i] = rsqrtf(1.0f + g_deg[i]);    // +1 = self-loop weight
    }
    if (i == 0) g_off[NN] = NE;
}

// ---------------- fill CSR (4 edges/thread), cursor atomics ---------------
// meta = (src, dinv[src]*w): dinv[dst] is applied inside the gathers, so
// fill does only ONE random load (dinv[r]) + one cursor atomic per edge.
__global__ void k_fill(const int* __restrict__ row,
                       const int* __restrict__ col,
                       const float* __restrict__ w) {
    int t = blockIdx.x * blockDim.x + threadIdx.x;   // over NE/4
    if (t < 128) g_sflag[t] = 0;                     // reset for next replay
    if (t >= NE / 4) return;
    int4   r4 = reinterpret_cast<const int4*>(row)[t];
    int4   c4 = reinterpret_cast<const int4*>(col)[t];
    float4 w4 = reinterpret_cast<const float4*>(w)[t];

    int p;
    p = atomicAdd(&g_cur[c4.x], 1);
    g_edge[p] = make_int2(r4.x, __float_as_int(g_dinv[r4.x] * w4.x));
    p = atomicAdd(&g_cur[c4.y], 1);
    g_edge[p] = make_int2(r4.y, __float_as_int(g_dinv[r4.y] * w4.y));
    p = atomicAdd(&g_cur[c4.z], 1);
    g_edge[p] = make_int2(r4.z, __float_as_int(g_dinv[r4.z] * w4.z));
    p = atomicAdd(&g_cur[c4.w], 1);
    g_edge[p] = make_int2(r4.w, __float_as_int(g_dinv[r4.w] * w4.w));
}

// ---------------- GEMM1: h = x @ W1   (100000x512 @ 512x16) ----------------
// R12 version (best measured: 86.9us). 128 rows/block, 2 threads/row x 8 cols,
// register double-buffered LDG pipeline, transposed smem stride 129, fp16 out.
__global__ void __launch_bounds__(256) k_gemm1(const float* __restrict__ x,
                                               const float* __restrict__ W1) {
    __shared__ float  Xs[32 * 129];   // [kk][r], stride 129: conflict-free
    __shared__ float4 Ws4[128];       // 32 x 16 W chunk as float4

    const int tid  = threadIdx.x;
    const int rloc = tid & 127;
    const int half = tid >> 7;                 // 0: j 0..7, 1: j 8..15
    const int row0 = blockIdx.x * 128;
    const int row  = row0 + rloc;

    float acc[8];
#pragma unroll
    for (int j = 0; j < 8; j++) acc[j] = 0.0f;

    float4 buf[4];
#pragma unroll
    for (int i = 0; i < 4; i++) {
        int idx = i * 256 + tid;
        int r   = idx >> 3;
        int q   = idx & 7;
        int gr  = row0 + r;
        buf[i] = (gr < NN)
            ? *reinterpret_cast<const float4*>(x + (size_t)gr * DF + q * 4)
            : make_float4(0.f, 0.f, 0.f, 0.f);
    }

    for (int c = 0; c < DF / 32; c++) {
        __syncthreads();
#pragma unroll
        for (int i = 0; i < 4; i++) {
            int idx = i * 256 + tid;
            int r   = idx >> 3;
            int kk  = (idx & 7) * 4;
            Xs[(kk + 0) * 129 + r] = buf[i].x;
            Xs[(kk + 1) * 129 + r] = buf[i].y;
            Xs[(kk + 2) * 129 + r] = buf[i].z;
            Xs[(kk + 3) * 129 + r] = buf[i].w;
        }
        if (tid < 128)
            Ws4[tid] = reinterpret_cast<const float4*>(W1)[c * 128 + tid];
        __syncthreads();

        if (c < DF / 32 - 1) {
#pragma unroll
            for (int i = 0; i < 4; i++) {
                int idx = i * 256 + tid;
                int r   = idx >> 3;
                int q   = idx & 7;
                int gr  = row0 + r;
                buf[i] = (gr < NN)
                    ? *reinterpret_cast<const float4*>(
                          x + (size_t)gr * DF + (c + 1) * 32 + q * 4)
                    : make_float4(0.f, 0.f, 0.f, 0.f);
            }
        }

#pragma unroll
        for (int kk = 0; kk < 32; kk++) {
            float  xv = Xs[kk * 129 + rloc];
            float4 w0 = Ws4[kk * 4 + half * 2 + 0];
            float4 w1 = Ws4[kk * 4 + half * 2 + 1];
            acc[0] += xv * w0.x;  acc[1] += xv * w0.y;
            acc[2] += xv * w0.z;  acc[3] += xv * w0.w;
            acc[4] += xv * w1.x;  acc[5] += xv * w1.y;
            acc[6] += xv * w1.z;  acc[7] += xv * w1.w;
        }
    }

    if (row < NN) {
        __half2 p0 = __floats2half2_rn(acc[0], acc[1]);
        __half2 p1 = __floats2half2_rn(acc[2], acc[3]);
        __half2 p2 = __floats2half2_rn(acc[4], acc[5]);
        __half2 p3 = __floats2half2_rn(acc[6], acc[7]);
        __half2* hp = &g_h[row * 8 + half * 4];
        reinterpret_cast<uint4*>(hp)[0] =
            make_uint4(*reinterpret_cast<unsigned*>(&p0),
                       *reinterpret_cast<unsigned*>(&p1),
                       *reinterpret_cast<unsigned*>(&p2),
                       *reinterpret_cast<unsigned*>(&p3));
    }
}

// ---------------- cooperative gather (fp16 src): 4 lanes per node ---------
// meta.y = dinv[src]*w; dst-side dinv applied once to the edge sum:
// out = d * Σ nm·h[src]  +  d² · h[n]
__device__ __forceinline__ float4 gather_quarter_h2(const __half2* __restrict__ src,
                                                    int n, int q, unsigned gmask,
                                                    int base) {
    float d = g_dinv[n];
    uint2 raw = *reinterpret_cast<const uint2*>(&src[n * 8 + q * 2]);
    float2 lo = __half22float2(*reinterpret_cast<__half2*>(&raw.x));
    float2 hi = __half22float2(*reinterpret_cast<__half2*>(&raw.y));
    float4 accE = make_float4(0.f, 0.f, 0.f, 0.f);   // edge sum (un-scaled)

    int k0  = g_off[n];
    int end = g_off[n + 1];
    for (int k = k0; k < end; k += 4) {
        int kk = k + q;
        int2 e = (kk < end) ? g_edge[kk] : make_int2(0, 0);   // norm 0 -> no-op
#pragma unroll
        for (int j = 0; j < 4; j++) {
            int   rs = __shfl_sync(gmask, e.x, base + j);
            float nm = __shfl_sync(gmask, __int_as_float(e.y), base + j);
            uint2 v = *reinterpret_cast<const uint2*>(&src[rs * 8 + q * 2]);
            float2 vlo = __half22float2(*reinterpret_cast<__half2*>(&v.x));
            float2 vhi = __half22float2(*reinterpret_cast<__half2*>(&v.y));
            accE.x += nm * vlo.x;
            accE.y += nm * vlo.y;
            accE.z += nm * vhi.x;
            accE.w += nm * vhi.y;
        }
    }
    float s = d * d;
    return make_float4(d * accE.x + s * lo.x,
                       d * accE.y + s * lo.y,
                       d * accE.z + s * hi.x,
                       d * accE.w + s * hi.y);
}

// ---------------- layer-1 propagate (+bias+relu): g_h -> g_h1 -------------
// Also resets g_cnt / g_deg (consumed by k_scan) for the next graph replay.
__global__ void k_gather1(const float* __restrict__ b1) {
    int t = blockIdx.x * blockDim.x + threadIdx.x;   // over NN*4
    if (t >= NN * 4) return;
    int n = t >> 2;
    int q = t & 3;
    if (q == 0) { g_cnt[n] = 0; g_deg[n] = 0.0f; }   // state reset for next run
    int lane = threadIdx.x & 31;
    int base = lane & ~3;
    unsigned gmask = 0xFu << base;

    float4 acc = gather_quarter_h2(g_h, n, q, gmask, base);
    float4 bb = reinterpret_cast<const float4*>(b1)[q];
    float4 o;
    o.x = fmaxf(acc.x + bb.x, 0.0f);
    o.y = fmaxf(acc.y + bb.y, 0.0f);
    o.z = fmaxf(acc.z + bb.z, 0.0f);
    o.w = fmaxf(acc.w + bb.w, 0.0f);
    __half2 p0 = __floats2half2_rn(o.x, o.y);
    __half2 p1 = __floats2half2_rn(o.z, o.w);
    reinterpret_cast<uint2*>(&g_h1[n * 8 + q * 2])[0] =
        make_uint2(*reinterpret_cast<unsigned*>(&p0),
                   *reinterpret_cast<unsigned*>(&p1));
}

// ---------------- layer-2 propagate fused with GEMM2 ----------------------
__global__ void __launch_bounds__(256) k_gather2_gemm2(
        const float* __restrict__ W2,
        const float* __restrict__ b2,
        float* __restrict__ out) {
    __shared__ float W2s[NH * NC];   // 640 floats
    __shared__ float b2s[NC];

    int tid = threadIdx.x;
#pragma unroll
    for (int i = tid; i < NH * NC; i += 256) W2s[i] = W2[i];
    if (tid < NC) b2s[tid] = b2[tid];
    __syncthreads();

    int t  = blockIdx.x * blockDim.x + tid;          // over NN*4 (padded)
    int n  = t >> 2;
    int q  = t & 3;
    bool valid = (n < NN);
    int nc = valid ? n : (NN - 1);                   // clamp: keep lanes alive
    int lane = tid & 31;
    int base = lane & ~3;
    unsigned gmask = 0xFu << base;

    float4 acc = gather_quarter_h2(g_h1, nc, q, gmask, base);

    // exchange quarters among the 4 node-lanes
    float hv[NH];
#pragma unroll
    for (int j = 0; j < 4; j++) {
        hv[j * 4 + 0] = __shfl_sync(gmask, acc.x, base + j);
        hv[j * 4 + 1] = __shfl_sync(gmask, acc.y, base + j);
        hv[j * 4 + 2] = __shfl_sync(gmask, acc.z, base + j);
        hv[j * 4 + 3] = __shfl_sync(gmask, acc.w, base + j);
    }

    // each lane: 10 columns [q*10, q*10+10)
    float o[10];
#pragma unroll
    for (int j = 0; j < 10; j++) o[j] = b2s[q * 10 + j];
#pragma unroll
    for (int k = 0; k < NH; k++) {
        float hk = hv[k];
        const float* wr = &W2s[k * NC + q * 10];
#pragma unroll
        for (int j = 0; j < 10; j++) o[j] += hk * wr[j];
    }

    if (valid) {
        float* op = out + (size_t)n * NC + q * 10;   // 8B aligned
#pragma unroll
        for (int j = 0; j < 5; j++)
            reinterpret_cast<float2*>(op)[j] = make_float2(o[2*j], o[2*j+1]);
    }
}

// ---------------- launch ----------------
// Fork-join overlap, R11 submission order (gemm1 first on side stream).
// Profiler slot 4 = k_fill -> direct verification of the fill traffic cut.
extern "C" void kernel_launch(void* const* d_in, const int* in_sizes, int n_in,
                              void* d_out, int out_size) {
    const float* x  = (const float*)d_in[0];
    const int*   ei = (const int*)  d_in[1];   // [2, NE]
    const float* w  = (const float*)d_in[2];
    const float* W1 = (const float*)d_in[3];
    const float* b1 = (const float*)d_in[4];
    const float* W2 = (const float*)d_in[5];
    const float* b2 = (const float*)d_in[6];
    float* out = (float*)d_out;

    const int* row = ei;
    const int* col = ei + NE;

    const int TB = 256;
    const int gE4 = (NE / 4 + TB - 1) / TB;          // 3125
    const int gN4 = (NN * 4 + TB - 1) / TB;          // 1563
    const int gG1 = (NN + 127) / 128;                // 782

    cudaStream_t s1;
    cudaStreamCreateWithFlags(&s1, cudaStreamNonBlocking);
    cudaEvent_t eFork, eJoin;
    cudaEventCreateWithFlags(&eFork, cudaEventDisableTiming);
    cudaEventCreateWithFlags(&eJoin, cudaEventDisableTiming);

    // fork: gemm1 on side stream (submission 1), concurrent with build
    cudaEventRecord(eFork, 0);
    cudaStreamWaitEvent(s1, eFork, 0);
    k_gemm1<<<gG1, TB, 0, s1>>>(x, W1);
    cudaEventRecord(eJoin, s1);

    // CSR build on main stream (submissions 2-4; slot 4 = fill -> profiled)
    k_count<<<gE4, TB>>>(col, w);
    k_scan <<<NSCAN, 1024>>>();
    k_fill <<<gE4, TB>>>(row, col, w);

    // join: gathers need both g_h (gemm1) and CSR
    cudaStreamWaitEvent(0, eJoin, 0);
    k_gather1<<<gN4, TB>>>(b1);
    k_gather2_gemm2<<<gN4, TB>>>(W2, b2, out);
}